// round 1
// baseline (speedup 1.0000x reference)
#include <cuda_runtime.h>
#include <cuda_bf16.h>
#include <math.h>

// Problem constants
#define BB 32
#define HH 64
#define WW 64
#define DD 8     // input capsule dim
#define CC 8     // input capsule types
#define DIMO 8   // output capsule dim
#define NCHO 8   // output capsule types

// v scratch: [B][H][W][n*8+d]  (group-major for FeaExt)
__device__ float g_v[BB * HH * WW * 64];

// ---------------------------------------------------------------------------
// Kernel 1: ConvTrans (grouped 3x3) + attention softmax + weighted sum -> v
// Block: 8x8 pixel tile. blockDim (64, 8) = 512 threads.
//   tx = c*8 + dh  (c = input type, dh = output dim of ConvTrans)
//   ty = pixel column within tile; thread owns all 8 rows of that column.
// ---------------------------------------------------------------------------
// Dynamic smem layout (floats):
//   s_in : 10*10*64          = 6400
//   s_u  : 64 px * 512       = 32768   u[pix][(d*8+c)*8 + n]
//   s_w  : 8*512             = 4096    one 3x3-tap weight slab
//   s_lg : 64 px * 64        = 4096    attention logits [pix][o*8+n]
//   s_at : 64 px * 64        = 4096    attention weights [pix][o*8+n]
#define K1_SMEM_FLOATS (6400 + 32768 + 4096 + 4096 + 4096)
#define K1_SMEM_BYTES  (K1_SMEM_FLOATS * 4)

__global__ __launch_bounds__(512, 1)
void convcaps_k1(const float* __restrict__ x,    // [B,H,W,D,C]  ch = d*8+c
                 const float* __restrict__ AW,   // [D,C,64]     (d*8+c)*64 + n*8+o
                 const float* __restrict__ CTW,  // [9,8,512]    tap*4096 + din*512 + (c*64+dh*8+n)
                 const float* __restrict__ CTB)  // [512]
{
    extern __shared__ float sm[];
    float* s_in = sm;                 // 6400
    float* s_u  = s_in + 6400;        // 32768
    float* s_w  = s_u + 32768;        // 4096
    float* s_lg = s_w + 4096;         // 4096
    float* s_at = s_lg + 4096;        // 4096

    const int tx = threadIdx.x;       // 0..63
    const int ty = threadIdx.y;       // 0..7
    const int tid = ty * 64 + tx;

    const int b  = blockIdx.z;
    const int h0 = blockIdx.y * 8;
    const int w0 = blockIdx.x * 8;

    // ---- load input tile with halo (zero pad) : 10x10 x 64ch ----
    for (int i = tid; i < 10 * 10 * 16; i += 512) {
        int q   = i & 15;
        int col = (i >> 4) % 10;
        int row = i / 160;
        int gh = h0 + row - 1;
        int gw = w0 + col - 1;
        float4 val = make_float4(0.f, 0.f, 0.f, 0.f);
        if ((unsigned)gh < (unsigned)HH && (unsigned)gw < (unsigned)WW) {
            val = *(const float4*)(x + (((size_t)(b * HH + gh) * WW + gw) * 64) + q * 4);
        }
        *(float4*)(s_in + (row * 10 + col) * 64 + q * 4) = val;
    }

    // ---- ConvTrans: thread (c, dh) computes u[dh][c][n=0..7] for its 8 pixels ----
    const int c  = tx >> 3;
    const int dh = tx & 7;

    float acc[8][8];
    {
        const float4* bp = (const float4*)(CTB + c * 64 + dh * 8);
        float4 b0 = __ldg(bp), b1 = __ldg(bp + 1);
        float bias[8] = {b0.x, b0.y, b0.z, b0.w, b1.x, b1.y, b1.z, b1.w};
        #pragma unroll
        for (int p = 0; p < 8; p++)
            #pragma unroll
            for (int n = 0; n < 8; n++)
                acc[p][n] = bias[n];
    }

    for (int tap = 0; tap < 9; tap++) {
        __syncthreads();  // also covers s_in readiness on first iter
        // stage this tap's weights: 8 din x 512 ch = 4096 floats
        {
            const float4* wp = (const float4*)(CTW) + tap * 1024;
            for (int i = tid; i < 1024; i += 512)
                ((float4*)s_w)[i] = __ldg(wp + i);
        }
        __syncthreads();

        const int ky = tap / 3, kx = tap % 3;
        #pragma unroll
        for (int din = 0; din < 8; din++) {
            float4 wa = *(float4*)(s_w + din * 512 + c * 64 + dh * 8);
            float4 wb = *(float4*)(s_w + din * 512 + c * 64 + dh * 8 + 4);
            float w[8] = {wa.x, wa.y, wa.z, wa.w, wb.x, wb.y, wb.z, wb.w};
            const float* inb = s_in + (ky * 10 + ty + kx) * 64 + din * 8 + c;
            #pragma unroll
            for (int py = 0; py < 8; py++) {
                float iv = inb[py * 640];
                #pragma unroll
                for (int n = 0; n < 8; n++)
                    acc[py][n] = fmaf(iv, w[n], acc[py][n]);
            }
        }
    }

    // ---- store u to smem: s_u[pix][(dh*8+c)*8 + n], pix = py*8 + ty ----
    #pragma unroll
    for (int py = 0; py < 8; py++) {
        float* up = s_u + (py * 8 + ty) * 512 + (dh * 8 + c) * 8;
        *(float4*)(up)     = make_float4(acc[py][0], acc[py][1], acc[py][2], acc[py][3]);
        *(float4*)(up + 4) = make_float4(acc[py][4], acc[py][5], acc[py][6], acc[py][7]);
    }
    __syncthreads();

    // ---- attention logits: thread = (o, n), 8 pixels (pix = k*8+ty) ----
    {
        const int o = tx >> 3, n = tx & 7;
        float lg[8] = {0.f, 0.f, 0.f, 0.f, 0.f, 0.f, 0.f, 0.f};
        for (int dc = 0; dc < 64; dc++) {
            float a = __ldg(AW + dc * 64 + n * 8 + o);
            #pragma unroll
            for (int k = 0; k < 8; k++)
                lg[k] = fmaf(s_u[(k * 8 + ty) * 512 + dc * 8 + n], a, lg[k]);
        }
        #pragma unroll
        for (int k = 0; k < 8; k++)
            s_lg[(k * 8 + ty) * 64 + o * 8 + n] = lg[k];
    }
    __syncthreads();

    // ---- softmax over o (input types): thread (o,n) writes att[o][n] ----
    {
        const int o = tx >> 3, n = tx & 7;
        #pragma unroll
        for (int k = 0; k < 8; k++) {
            const float* lp = s_lg + (k * 8 + ty) * 64 + n;
            float l[8];
            float m = -1e30f;
            #pragma unroll
            for (int j = 0; j < 8; j++) { l[j] = lp[j * 8]; m = fmaxf(m, l[j]); }
            float s = 0.f;
            float eo = 0.f;
            #pragma unroll
            for (int j = 0; j < 8; j++) {
                float e = __expf(l[j] - m);
                s += e;
                if (j == o) eo = e;
            }
            s_at[(k * 8 + ty) * 64 + o * 8 + n] = eo / s;
        }
    }
    __syncthreads();

    // ---- v[d][n] = sum_o u[d][o][n] * att[o][n]; write to g_v ch = n*8+d ----
    {
        const int d = tx >> 3, n = tx & 7;
        #pragma unroll
        for (int k = 0; k < 8; k++) {
            const int pix = k * 8 + ty;
            float v = 0.f;
            #pragma unroll
            for (int o = 0; o < 8; o++)
                v = fmaf(s_u[pix * 512 + (d * 8 + o) * 8 + n],
                         s_at[pix * 64 + o * 8 + n], v);
            int gh = h0 + k, gw = w0 + ty;
            g_v[((size_t)(b * HH + gh) * WW + gw) * 64 + n * 8 + d] = v;
        }
    }
}

// ---------------------------------------------------------------------------
// Kernel 2: FeaExt (grouped 3x3) + ReLU + CapsAct (grouped 1x1) -> out
// Block: 8x8 tile, 512 threads: thread = (pixel 0..63, n 0..7)
// ---------------------------------------------------------------------------
__global__ __launch_bounds__(512, 2)
void convcaps_k2(const float* __restrict__ FW,  // [9,8,64]  tap*512 + d*64 + (n*8+e)
                 const float* __restrict__ FB,  // [64]
                 const float* __restrict__ CW,  // [8,64]    e*64 + (n*8+f)
                 const float* __restrict__ CB,  // [64]
                 float* __restrict__ out)       // [B,H,W,64] ch = f*8+n
{
    __shared__ float s_v[10 * 10 * 64];   // 6400
    __shared__ float s_fw[9 * 8 * 64];    // 4608
    __shared__ float s_cw[8 * 64];        // 512
    __shared__ float s_fb[64];
    __shared__ float s_cb[64];

    const int tid = threadIdx.x;
    const int b  = blockIdx.z;
    const int h0 = blockIdx.y * 8;
    const int w0 = blockIdx.x * 8;

    // load v tile with halo
    for (int i = tid; i < 10 * 10 * 16; i += 512) {
        int q   = i & 15;
        int col = (i >> 4) % 10;
        int row = i / 160;
        int gh = h0 + row - 1;
        int gw = w0 + col - 1;
        float4 val = make_float4(0.f, 0.f, 0.f, 0.f);
        if ((unsigned)gh < (unsigned)HH && (unsigned)gw < (unsigned)WW) {
            val = *(const float4*)(g_v + (((size_t)(b * HH + gh) * WW + gw) * 64) + q * 4);
        }
        *(float4*)(s_v + (row * 10 + col) * 64 + q * 4) = val;
    }
    // load weights
    for (int i = tid; i < 1152; i += 512) ((float4*)s_fw)[i] = __ldg((const float4*)FW + i);
    for (int i = tid; i < 128;  i += 512) ((float4*)s_cw)[i] = __ldg((const float4*)CW + i);
    if (tid < 64) { s_fb[tid] = __ldg(FB + tid); s_cb[tid] = __ldg(CB + tid); }
    __syncthreads();

    const int pix = tid >> 3;      // 0..63
    const int n   = tid & 7;
    const int pr = pix >> 3, pc = pix & 7;

    float h1[8];
    {
        const float* fb = s_fb + n * 8;
        #pragma unroll
        for (int e = 0; e < 8; e++) h1[e] = fb[e];
    }

    #pragma unroll
    for (int tap = 0; tap < 9; tap++) {
        const int ky = tap / 3, kx = tap % 3;
        const float* ivb = s_v + ((pr + ky) * 10 + pc + kx) * 64 + n * 8;
        #pragma unroll
        for (int d = 0; d < 8; d++) {
            float iv = ivb[d];
            const float* wp = s_fw + (tap * 8 + d) * 64 + n * 8;
            #pragma unroll
            for (int e = 0; e < 8; e++)
                h1[e] = fmaf(iv, wp[e], h1[e]);
        }
    }
    #pragma unroll
    for (int e = 0; e < 8; e++) h1[e] = fmaxf(h1[e], 0.f);

    float h2[8];
    {
        const float* cb = s_cb + n * 8;
        #pragma unroll
        for (int f = 0; f < 8; f++) h2[f] = cb[f];
    }
    #pragma unroll
    for (int e = 0; e < 8; e++) {
        const float* cw = s_cw + e * 64 + n * 8;
        float he = h1[e];
        #pragma unroll
        for (int f = 0; f < 8; f++)
            h2[f] = fmaf(he, cw[f], h2[f]);
    }

    const int gh = h0 + pr, gw = w0 + pc;
    float* ob = out + ((size_t)(b * HH + gh) * WW + gw) * 64;
    #pragma unroll
    for (int f = 0; f < 8; f++)
        ob[f * 8 + n] = h2[f];
}

// ---------------------------------------------------------------------------
extern "C" void kernel_launch(void* const* d_in, const int* in_sizes, int n_in,
                              void* d_out, int out_size) {
    (void)in_sizes; (void)n_in; (void)out_size;
    const float* x   = (const float*)d_in[0];
    const float* AW  = (const float*)d_in[1];
    const float* CTW = (const float*)d_in[2];
    const float* CTB = (const float*)d_in[3];
    const float* FW  = (const float*)d_in[4];
    const float* FB  = (const float*)d_in[5];
    const float* CW  = (const float*)d_in[6];
    const float* CB  = (const float*)d_in[7];

    cudaFuncSetAttribute(convcaps_k1,
                         cudaFuncAttributeMaxDynamicSharedMemorySize, K1_SMEM_BYTES);

    dim3 grid(WW / 8, HH / 8, BB);
    convcaps_k1<<<grid, dim3(64, 8), K1_SMEM_BYTES>>>(x, AW, CTW, CTB);
    convcaps_k2<<<grid, 512>>>(FW, FB, CW, CB, (float*)d_out);
}